// round 14
// baseline (speedup 1.0000x reference)
#include <cuda_runtime.h>
#include <cuda_fp16.h>
#include <cstdint>

#define NN 50000
#define NE 800000
#define DD 512
#define NL 3
#define LN_EPS 1e-5f
#define SCAN_NB 49   // ceil(NN/1024)

// per-stage smem: A 16K | B 16K = 32 KB; 3 stages (BK=64)
#define STG_BYTES 32768
#define NSTAGE 3
#define SMEM_TOT (NSTAGE * STG_BYTES)

#define WPAIRS (NL * DD * DD / 2)
#define XPAIRS (NN * DD / 2)

// Scratch (device globals — no allocation allowed)
__device__ __half g_ht[NN * DD];           // GEMM output (fp16 storage)
__device__ __half g_a[NN * DD];            // layer input (fp16)
__device__ __half g_W[NL * DD * DD];       // weights (fp16)
__device__ float g_deg[NN];
__device__ float g_isq[NN];
__device__ int   g_row_off[NN + 1];
__device__ int   g_cursor[NN];
__device__ int   g_csr_src[NE];
__device__ int   g_blksum[SCAN_NB];

// ---------------------------------------------------------------------------
// Fused fp16 conversion: W pairs first, then X pairs.
// ---------------------------------------------------------------------------
__global__ void k_conv(const float* __restrict__ Ws, const float* __restrict__ x) {
    size_t i = (size_t)blockIdx.x * 256 + threadIdx.x;
    if (i < WPAIRS) {
        float2 v = reinterpret_cast<const float2*>(Ws)[i];
        reinterpret_cast<__half2*>(g_W)[i] = __floats2half2_rn(v.x, v.y);
    } else if (i < WPAIRS + XPAIRS) {
        size_t j = i - WPAIRS;
        float2 v = reinterpret_cast<const float2*>(x)[j];
        reinterpret_cast<__half2*>(g_a)[j] = __floats2half2_rn(v.x, v.y);
    }
}

// ---------------------------------------------------------------------------
// Degree / CSR preprocessing (side stream; only k_agg_ln depends on it)
// ---------------------------------------------------------------------------
__global__ void k_deg_init() {
    int i = blockIdx.x * blockDim.x + threadIdx.x;
    if (i < NN) g_deg[i] = 1.0f;
}
__global__ void k_deg_accum(const int* __restrict__ dst) {
    int e = blockIdx.x * blockDim.x + threadIdx.x;
    if (e < NE) atomicAdd(&g_deg[dst[e]], 1.0f);
}

// scan1: per-block exclusive scan + isq = rsqrt(deg); block sums to g_blksum
__global__ void k_scan1() {
    __shared__ int wsum[32];
    int b = blockIdx.x, t = threadIdx.x, w = t >> 5, l = t & 31;
    int idx = b * 1024 + t;
    float dg = (idx < NN) ? g_deg[idx] : 1.0f;
    if (idx < NN) g_isq[idx] = rsqrtf(dg);
    int c = (idx < NN) ? (int)(dg - 1.0f) : 0;
    int incl = c;
    #pragma unroll
    for (int o = 1; o < 32; o <<= 1) {
        int v = __shfl_up_sync(0xffffffffu, incl, o);
        if (l >= o) incl += v;
    }
    if (l == 31) wsum[w] = incl;
    __syncthreads();
    if (w == 0) {
        int v = wsum[l];
        #pragma unroll
        for (int o = 1; o < 32; o <<= 1) {
            int u = __shfl_up_sync(0xffffffffu, v, o);
            if (l >= o) v += u;
        }
        wsum[l] = v;
    }
    __syncthreads();
    int excl = (w ? wsum[w - 1] : 0) + incl - c;
    if (idx < NN) g_row_off[idx] = excl;
    if (t == 1023) g_blksum[b] = wsum[31];
}

// scan3: each block computes its own block-offset prefix (49 values) in-register
__global__ void k_scan3() {
    __shared__ int s_off[2], s_tot[2];
    int b = blockIdx.x, t = threadIdx.x;
    if (t < 64) {
        int w = t >> 5, l = t & 31;
        int v  = (t < SCAN_NB) ? g_blksum[t] : 0;
        int vb = (t < b) ? v : 0;
        #pragma unroll
        for (int o = 16; o > 0; o >>= 1) {
            vb += __shfl_xor_sync(0xffffffffu, vb, o);
            v  += __shfl_xor_sync(0xffffffffu, v, o);
        }
        if (l == 0) { s_off[w] = vb; s_tot[w] = v; }
    }
    __syncthreads();
    int off = s_off[0] + s_off[1];
    int idx = b * 1024 + t;
    if (idx < NN) {
        int r = g_row_off[idx] + off;
        g_row_off[idx] = r;
        g_cursor[idx]  = r;
    }
    if (b == SCAN_NB - 1 && t == 0) g_row_off[NN] = s_tot[0] + s_tot[1];
}

__global__ void k_fill(const int* __restrict__ src, const int* __restrict__ dst) {
    int e = blockIdx.x * blockDim.x + threadIdx.x;
    if (e < NE) {
        int p = atomicAdd(&g_cursor[dst[e]], 1);
        g_csr_src[p] = src[e];
    }
}

// ---------------------------------------------------------------------------
// Tensor-core GEMM, single fp16 term, fp16-accumulator chains of 2 MMAs
// (K=32) drained into fp32 accumulators.
// BM=128, BN=128, BK=64; 8 warps (4m x 2n), 32x64/warp; 3-stage cp.async.
// ---------------------------------------------------------------------------
__device__ __forceinline__ uint32_t swzA(uint32_t a) { return a ^ ((a >> 3) & 0x70); }
__device__ __forceinline__ uint32_t swzB(uint32_t a) { return a ^ ((a >> 4) & 0x70); }

__device__ __forceinline__ void cpa16(uint32_t s, const void* g, int sz) {
    asm volatile("cp.async.cg.shared.global [%0], [%1], 16, %2;"
                 :: "r"(s), "l"(g), "r"(sz));
}
__device__ __forceinline__ void ldsm_x4(uint32_t* r, uint32_t addr) {
    asm volatile("ldmatrix.sync.aligned.m8n8.x4.shared.b16 {%0,%1,%2,%3}, [%4];"
                 : "=r"(r[0]), "=r"(r[1]), "=r"(r[2]), "=r"(r[3]) : "r"(addr));
}
__device__ __forceinline__ void ldsm_x4_t(uint32_t* r, uint32_t addr) {
    asm volatile("ldmatrix.sync.aligned.m8n8.x4.trans.shared.b16 {%0,%1,%2,%3}, [%4];"
                 : "=r"(r[0]), "=r"(r[1]), "=r"(r[2]), "=r"(r[3]) : "r"(addr));
}
// fp16-accumulator MMA: d,c are 2 b32 regs (4 halves)
__device__ __forceinline__ void mma16816h(uint32_t* c, const uint32_t* a, const uint32_t* b) {
    asm volatile("mma.sync.aligned.m16n8k16.row.col.f16.f16.f16.f16 "
                 "{%0,%1}, {%2,%3,%4,%5}, {%6,%7}, {%0,%1};"
                 : "+r"(c[0]), "+r"(c[1])
                 : "r"(a[0]), "r"(a[1]), "r"(a[2]), "r"(a[3]), "r"(b[0]), "r"(b[1]));
}

__global__ __launch_bounds__(256, 2) void k_gemm(int l, const float* __restrict__ bias) {
    extern __shared__ __align__(128) unsigned char sm[];
    uint32_t sbase = (uint32_t)__cvta_generic_to_shared(sm);

    const __half* __restrict__ A = g_a;
    const __half* __restrict__ W = g_W + (size_t)l * DD * DD;

    int t = threadIdx.x;
    int lane = t & 31;
    int warp = t >> 5;
    int m0 = blockIdx.x * 128;
    int n0 = blockIdx.y * 128;
    int wm = (warp & 3) * 32;
    int wn = (warp >> 2) * 64;

    float acc[2][8][4];
    #pragma unroll
    for (int i = 0; i < 2; i++)
        #pragma unroll
        for (int j = 0; j < 8; j++)
            #pragma unroll
            for (int q = 0; q < 4; q++) acc[i][j][q] = 0.f;

    // cp.async load mappings: A tile 128 rows x 128B; B tile 64 rows x 256B.
    auto issue = [&](int kb) {
        uint32_t so = sbase + (uint32_t)(kb % NSTAGE) * STG_BYTES;
        #pragma unroll
        for (int i = 0; i < 4; i++) {
            int c = t + 256 * i;
            int row = c >> 3, u = c & 7;
            int gr = m0 + row;
            int sz = (gr < NN) ? 16 : 0;
            size_t gidx = (size_t)(gr < NN ? gr : 0) * DD + kb * 64 + u * 8;
            cpa16(so + swzA((uint32_t)row * 128 + u * 16), &A[gidx], sz);
        }
        #pragma unroll
        for (int i = 0; i < 4; i++) {
            int c = t + 256 * i;
            int row = c >> 4, u = c & 15;
            size_t gidx = (size_t)(kb * 64 + row) * DD + n0 + u * 8;
            cpa16(so + 16384 + swzB((uint32_t)row * 256 + u * 16), &W[gidx], 16);
        }
    };

    const int NIT = DD / 64;  // 8
    issue(0);
    asm volatile("cp.async.commit_group;");
    issue(1);
    asm volatile("cp.async.commit_group;");

    for (int kb = 0; kb < NIT; kb++) {
        if (kb + 2 < NIT) {
            issue(kb + 2);
            asm volatile("cp.async.commit_group;");
            asm volatile("cp.async.wait_group 2;");
        } else if (kb + 2 == NIT) {
            asm volatile("cp.async.wait_group 1;");
        } else {
            asm volatile("cp.async.wait_group 0;");
        }
        __syncthreads();

        uint32_t so = sbase + (uint32_t)(kb % NSTAGE) * STG_BYTES;
        uint32_t sA = so, sB = so + 16384;

        // Two K=32 half-stages; fp16 accumulation within, fp32 drain after.
        #pragma unroll
        for (int h = 0; h < 2; h++) {
            uint32_t ah[2][2][4];
            #pragma unroll
            for (int ksu = 0; ksu < 2; ksu++) {
                int k = (h * 2 + ksu) * 16;
                #pragma unroll
                for (int mi = 0; mi < 2; mi++) {
                    uint32_t ad = (uint32_t)(wm + mi * 16 + (lane & 15)) * 128
                                + (uint32_t)(k + 8 * (lane >> 4)) * 2;
                    ldsm_x4(ah[ksu][mi], sA + swzA(ad));
                }
            }
            #pragma unroll
            for (int nj = 0; nj < 4; nj++) {
                uint32_t bh[2][4];
                #pragma unroll
                for (int ksu = 0; ksu < 2; ksu++) {
                    int k = (h * 2 + ksu) * 16;
                    uint32_t bd = (uint32_t)(k + (lane & 15)) * 256
                                + (uint32_t)(wn + nj * 16 + 8 * (lane >> 4)) * 2;
                    ldsm_x4_t(bh[ksu], sB + swzB(bd));
                }
                uint32_t ch[4][2];
                #pragma unroll
                for (int q = 0; q < 4; q++) { ch[q][0] = 0u; ch[q][1] = 0u; }
                #pragma unroll
                for (int ksu = 0; ksu < 2; ksu++)
                    #pragma unroll
                    for (int mi = 0; mi < 2; mi++)
                        #pragma unroll
                        for (int hf = 0; hf < 2; hf++)
                            mma16816h(ch[mi * 2 + hf], ah[ksu][mi], bh[ksu] + 2 * hf);
                #pragma unroll
                for (int mi = 0; mi < 2; mi++)
                    #pragma unroll
                    for (int hf = 0; hf < 2; hf++) {
                        float* a = acc[mi][nj * 2 + hf];
                        float2 lo = __half22float2(
                            *reinterpret_cast<__half2*>(&ch[mi * 2 + hf][0]));
                        float2 hi = __half22float2(
                            *reinterpret_cast<__half2*>(&ch[mi * 2 + hf][1]));
                        a[0] += lo.x; a[1] += lo.y; a[2] += hi.x; a[3] += hi.y;
                    }
            }
        }
        __syncthreads();
    }

    // Epilogue: add bias, store fp16
    #pragma unroll
    for (int mi = 0; mi < 2; mi++) {
        #pragma unroll
        for (int nf = 0; nf < 8; nf++) {
            int row = m0 + wm + mi * 16 + (lane >> 2);
            int col = n0 + wn + nf * 8 + (lane & 3) * 2;
            float b0 = bias[col], b1 = bias[col + 1];
            float* c = acc[mi][nf];
            if (row < NN) {
                __half2 h = __floats2half2_rn(c[0] + b0, c[1] + b1);
                *reinterpret_cast<__half2*>(&g_ht[(size_t)row * DD + col]) = h;
            }
            if (row + 8 < NN) {
                __half2 h = __floats2half2_rn(c[2] + b0, c[3] + b1);
                *reinterpret_cast<__half2*>(&g_ht[(size_t)(row + 8) * DD + col]) = h;
            }
        }
    }
}

// ---------------------------------------------------------------------------
// FUSED: CSR gather-aggregate + self-loop + LayerNorm + ReLU.
// Gathers fp16 rows (16B = 8 halves per lane-chunk), accumulates in fp32.
// ---------------------------------------------------------------------------
__device__ __forceinline__ void acc_row8(float* a, uint4 v, float w) {
    float2 f0 = __half22float2(*reinterpret_cast<__half2*>(&v.x));
    float2 f1 = __half22float2(*reinterpret_cast<__half2*>(&v.y));
    float2 f2 = __half22float2(*reinterpret_cast<__half2*>(&v.z));
    float2 f3 = __half22float2(*reinterpret_cast<__half2*>(&v.w));
    a[0] += f0.x * w; a[1] += f0.y * w;
    a[2] += f1.x * w; a[3] += f1.y * w;
    a[4] += f2.x * w; a[5] += f2.y * w;
    a[6] += f3.x * w; a[7] += f3.y * w;
}

__global__ __launch_bounds__(256) void k_agg_ln(const float* __restrict__ gamma,
                                                const float* __restrict__ beta,
                                                float* __restrict__ out, int to_out) {
    int row = blockIdx.x * 8 + (threadIdx.x >> 5);
    if (row >= NN) return;
    int lane = threadIdx.x & 31;

    float isq_r = g_isq[row];

    float acc[2][8];
    {
        const uint4* ph = reinterpret_cast<const uint4*>(&g_ht[(size_t)row * DD]);
        #pragma unroll
        for (int j = 0; j < 2; j++) {
            #pragma unroll
            for (int q = 0; q < 8; q++) acc[j][q] = 0.f;
            acc_row8(acc[j], ph[lane + 32 * j], isq_r);
        }
    }

    int e  = g_row_off[row];
    int e1 = g_row_off[row + 1];
    for (; e + 1 < e1; e += 2) {
        int s0 = g_csr_src[e];
        int s1 = g_csr_src[e + 1];
        float w0 = g_isq[s0];
        float w1 = g_isq[s1];
        const uint4* p0 = reinterpret_cast<const uint4*>(&g_ht[(size_t)s0 * DD]);
        const uint4* p1 = reinterpret_cast<const uint4*>(&g_ht[(size_t)s1 * DD]);
        #pragma unroll
        for (int j = 0; j < 2; j++) {
            uint4 v0 = p0[lane + 32 * j];
            uint4 v1 = p1[lane + 32 * j];
            acc_row8(acc[j], v0, w0);
            acc_row8(acc[j], v1, w1);
        }
    }
    if (e < e1) {
        int s0 = g_csr_src[e];
        float w0 = g_isq[s0];
        const uint4* p0 = reinterpret_cast<const uint4*>(&g_ht[(size_t)s0 * DD]);
        #pragma unroll
        for (int j = 0; j < 2; j++)
            acc_row8(acc[j], p0[lane + 32 * j], w0);
    }

    float sum = 0.f, sq = 0.f;
    #pragma unroll
    for (int j = 0; j < 2; j++)
        #pragma unroll
        for (int q = 0; q < 8; q++) {
            acc[j][q] *= isq_r;
            sum += acc[j][q];
            sq  += acc[j][q] * acc[j][q];
        }
    #pragma unroll
    for (int o = 16; o > 0; o >>= 1) {
        sum += __shfl_xor_sync(0xffffffffu, sum, o);
        sq  += __shfl_xor_sync(0xffffffffu, sq, o);
    }
    float mean = sum * (1.0f / DD);
    float var  = sq * (1.0f / DD) - mean * mean;
    float rstd = rsqrtf(var + LN_EPS);

    #pragma unroll
    for (int j = 0; j < 2; j++) {
        int col = (lane + 32 * j) * 8;
        float r[8];
        #pragma unroll
        for (int q = 0; q < 8; q++)
            r[q] = fmaxf(gamma[col + q] * (acc[j][q] - mean) * rstd + beta[col + q], 0.f);
        if (to_out) {
            float4* po = reinterpret_cast<float4*>(&out[(size_t)row * DD + col]);
            po[0] = make_float4(r[0], r[1], r[2], r[3]);
            po[1] = make_float4(r[4], r[5], r[6], r[7]);
        } else {
            size_t pidx = ((size_t)row * DD + col) >> 1;
            #pragma unroll
            for (int q = 0; q < 4; q++)
                reinterpret_cast<__half2*>(g_a)[pidx + q] =
                    __floats2half2_rn(r[2 * q], r[2 * q + 1]);
        }
    }
}

// ---------------------------------------------------------------------------
extern "C" void kernel_launch(void* const* d_in, const int* in_sizes, int n_in,
                              void* d_out, int out_size) {
    const float* x      = (const float*)d_in[0];   // [NN, DD]
    const int*   edge   = (const int*)  d_in[1];   // [2, NE]
    const float* Ws     = (const float*)d_in[2];   // [NL, DD, DD]
    const float* bs     = (const float*)d_in[3];   // [NL, DD]
    const float* gammas = (const float*)d_in[4];   // [NL, DD]
    const float* betas  = (const float*)d_in[5];   // [NL, DD]
    float* out = (float*)d_out;

    const int* src = edge;
    const int* dst = edge + NE;

    cudaFuncSetAttribute(k_gemm, cudaFuncAttributeMaxDynamicSharedMemorySize, SMEM_TOT);

    // Fork: CSR preprocessing runs on a side stream, overlapped with
    // k_conv + first GEMM. Joined before the first k_agg_ln (its only consumer).
    cudaStream_t s;
    cudaStreamCreateWithFlags(&s, cudaStreamNonBlocking);
    cudaEvent_t eFork, eJoin;
    cudaEventCreateWithFlags(&eFork, cudaEventDisableTiming);
    cudaEventCreateWithFlags(&eJoin, cudaEventDisableTiming);

    cudaEventRecord(eFork, 0);
    cudaStreamWaitEvent(s, eFork, 0);
    k_deg_init<<<(NN + 255) / 256, 256, 0, s>>>();
    k_deg_accum<<<(NE + 255) / 256, 256, 0, s>>>(dst);
    k_scan1<<<SCAN_NB, 1024, 0, s>>>();
    k_scan3<<<SCAN_NB, 1024, 0, s>>>();
    k_fill<<<(NE + 255) / 256, 256, 0, s>>>(src, dst);
    cudaEventRecord(eJoin, s);

    // Main chain
    k_conv<<<(WPAIRS + XPAIRS + 255) / 256, 256>>>(Ws, x);

    dim3 ggrid((NN + 127) / 128, DD / 128);
    k_gemm<<<ggrid, 256, SMEM_TOT>>>(0, bs);
    cudaStreamWaitEvent(0, eJoin, 0);   // CSR must be ready from here on
    k_agg_ln<<<(NN + 7) / 8, 256>>>(gammas, betas, out, 0);
    for (int l = 1; l < NL; l++) {
        k_gemm<<<ggrid, 256, SMEM_TOT>>>(l, bs + l * DD);
        k_agg_ln<<<(NN + 7) / 8, 256>>>(gammas + l * DD, betas + l * DD,
                                        out, l == NL - 1 ? 1 : 0);
    }

    cudaEventDestroy(eFork);
    cudaEventDestroy(eJoin);
    cudaStreamDestroy(s);
}

// round 15
// speedup vs baseline: 1.1512x; 1.1512x over previous
#include <cuda_runtime.h>
#include <cuda_fp16.h>
#include <cstdint>

#define NN 50000
#define NE 800000
#define DD 512
#define NL 3
#define LN_EPS 1e-5f
#define SCAN_NB 49   // ceil(NN/1024)

// per-stage smem: A 16K | B 16K = 32 KB; 3 stages (BK=64)
#define STG_BYTES 32768
#define NSTAGE 3
#define SMEM_TOT (NSTAGE * STG_BYTES)

#define WQUADS (NL * DD * DD / 4)
#define XQUADS (NN * DD / 4)

// Scratch (device globals — no allocation allowed)
__device__ __half g_ht[NN * DD];           // GEMM output (fp16 storage)
__device__ __half g_a[NN * DD];            // layer input (fp16)
__device__ __half g_W[NL * DD * DD];       // weights (fp16)
__device__ float g_deg[NN];
__device__ float g_isq[NN];
__device__ int   g_row_off[NN + 1];
__device__ int   g_cursor[NN];
__device__ int   g_csr_src[NE];
__device__ int   g_blksum[SCAN_NB];

// ---------------------------------------------------------------------------
// Fused fp16 conversion, float4-vectorized: W quads first, then X quads.
// ---------------------------------------------------------------------------
__global__ void k_conv(const float* __restrict__ Ws, const float* __restrict__ x) {
    size_t i = (size_t)blockIdx.x * 256 + threadIdx.x;   // quad index (4 floats)
    if (i < WQUADS) {
        float4 v = reinterpret_cast<const float4*>(Ws)[i];
        __half2 h0 = __floats2half2_rn(v.x, v.y);
        __half2 h1 = __floats2half2_rn(v.z, v.w);
        reinterpret_cast<__half2*>(g_W)[2 * i]     = h0;
        reinterpret_cast<__half2*>(g_W)[2 * i + 1] = h1;
    } else if (i < WQUADS + XQUADS) {
        size_t j = i - WQUADS;
        float4 v = reinterpret_cast<const float4*>(x)[j];
        __half2 h0 = __floats2half2_rn(v.x, v.y);
        __half2 h1 = __floats2half2_rn(v.z, v.w);
        reinterpret_cast<__half2*>(g_a)[2 * j]     = h0;
        reinterpret_cast<__half2*>(g_a)[2 * j + 1] = h1;
    }
}

// ---------------------------------------------------------------------------
// Degree / CSR preprocessing (side stream; only k_agg_ln depends on it)
// ---------------------------------------------------------------------------
__global__ void k_deg_init() {
    int i = blockIdx.x * blockDim.x + threadIdx.x;
    if (i < NN) g_deg[i] = 1.0f;
}
__global__ void k_deg_accum(const int* __restrict__ dst) {
    int e = blockIdx.x * blockDim.x + threadIdx.x;
    if (e < NE) atomicAdd(&g_deg[dst[e]], 1.0f);
}

// scan1: per-block exclusive scan + isq = rsqrt(deg); block sums to g_blksum
__global__ void k_scan1() {
    __shared__ int wsum[32];
    int b = blockIdx.x, t = threadIdx.x, w = t >> 5, l = t & 31;
    int idx = b * 1024 + t;
    float dg = (idx < NN) ? g_deg[idx] : 1.0f;
    if (idx < NN) g_isq[idx] = rsqrtf(dg);
    int c = (idx < NN) ? (int)(dg - 1.0f) : 0;
    int incl = c;
    #pragma unroll
    for (int o = 1; o < 32; o <<= 1) {
        int v = __shfl_up_sync(0xffffffffu, incl, o);
        if (l >= o) incl += v;
    }
    if (l == 31) wsum[w] = incl;
    __syncthreads();
    if (w == 0) {
        int v = wsum[l];
        #pragma unroll
        for (int o = 1; o < 32; o <<= 1) {
            int u = __shfl_up_sync(0xffffffffu, v, o);
            if (l >= o) v += u;
        }
        wsum[l] = v;
    }
    __syncthreads();
    int excl = (w ? wsum[w - 1] : 0) + incl - c;
    if (idx < NN) g_row_off[idx] = excl;
    if (t == 1023) g_blksum[b] = wsum[31];
}

// scan3: each block computes its own block-offset prefix (49 values) in-register
__global__ void k_scan3() {
    __shared__ int s_off[2], s_tot[2];
    int b = blockIdx.x, t = threadIdx.x;
    if (t < 64) {
        int w = t >> 5, l = t & 31;
        int v  = (t < SCAN_NB) ? g_blksum[t] : 0;
        int vb = (t < b) ? v : 0;
        #pragma unroll
        for (int o = 16; o > 0; o >>= 1) {
            vb += __shfl_xor_sync(0xffffffffu, vb, o);
            v  += __shfl_xor_sync(0xffffffffu, v, o);
        }
        if (l == 0) { s_off[w] = vb; s_tot[w] = v; }
    }
    __syncthreads();
    int off = s_off[0] + s_off[1];
    int idx = b * 1024 + t;
    if (idx < NN) {
        int r = g_row_off[idx] + off;
        g_row_off[idx] = r;
        g_cursor[idx]  = r;
    }
    if (b == SCAN_NB - 1 && t == 0) g_row_off[NN] = s_tot[0] + s_tot[1];
}

__global__ void k_fill(const int* __restrict__ src, const int* __restrict__ dst) {
    int e = blockIdx.x * blockDim.x + threadIdx.x;
    if (e < NE) {
        int p = atomicAdd(&g_cursor[dst[e]], 1);
        g_csr_src[p] = src[e];
    }
}

// ---------------------------------------------------------------------------
// Tensor-core GEMM, single fp16 term: acc += A*B.
// BM=128, BN=128, BK=64; 8 warps (4m x 2n), 32x64/warp; 3-stage cp.async.
// Output stored as fp16.
// ---------------------------------------------------------------------------
__device__ __forceinline__ uint32_t swzA(uint32_t a) { return a ^ ((a >> 3) & 0x70); }
__device__ __forceinline__ uint32_t swzB(uint32_t a) { return a ^ ((a >> 4) & 0x70); }

__device__ __forceinline__ void cpa16(uint32_t s, const void* g, int sz) {
    asm volatile("cp.async.cg.shared.global [%0], [%1], 16, %2;"
                 :: "r"(s), "l"(g), "r"(sz));
}
__device__ __forceinline__ void ldsm_x4(uint32_t* r, uint32_t addr) {
    asm volatile("ldmatrix.sync.aligned.m8n8.x4.shared.b16 {%0,%1,%2,%3}, [%4];"
                 : "=r"(r[0]), "=r"(r[1]), "=r"(r[2]), "=r"(r[3]) : "r"(addr));
}
__device__ __forceinline__ void ldsm_x4_t(uint32_t* r, uint32_t addr) {
    asm volatile("ldmatrix.sync.aligned.m8n8.x4.trans.shared.b16 {%0,%1,%2,%3}, [%4];"
                 : "=r"(r[0]), "=r"(r[1]), "=r"(r[2]), "=r"(r[3]) : "r"(addr));
}
__device__ __forceinline__ void mma16816(float* c, const uint32_t* a, const uint32_t* b) {
    asm volatile("mma.sync.aligned.m16n8k16.row.col.f32.f16.f16.f32 "
                 "{%0,%1,%2,%3}, {%4,%5,%6,%7}, {%8,%9}, {%0,%1,%2,%3};"
                 : "+f"(c[0]), "+f"(c[1]), "+f"(c[2]), "+f"(c[3])
                 : "r"(a[0]), "r"(a[1]), "r"(a[2]), "r"(a[3]), "r"(b[0]), "r"(b[1]));
}

__global__ __launch_bounds__(256, 2) void k_gemm(int l, const float* __restrict__ bias) {
    extern __shared__ __align__(128) unsigned char sm[];
    uint32_t sbase = (uint32_t)__cvta_generic_to_shared(sm);

    const __half* __restrict__ A = g_a;
    const __half* __restrict__ W = g_W + (size_t)l * DD * DD;

    int t = threadIdx.x;
    int lane = t & 31;
    int warp = t >> 5;
    int m0 = blockIdx.x * 128;
    int n0 = blockIdx.y * 128;
    int wm = (warp & 3) * 32;
    int wn = (warp >> 2) * 64;

    float acc[2][8][4];
    #pragma unroll
    for (int i = 0; i < 2; i++)
        #pragma unroll
        for (int j = 0; j < 8; j++)
            #pragma unroll
            for (int q = 0; q < 4; q++) acc[i][j][q] = 0.f;

    // cp.async load mappings: A tile 128 rows x 128B; B tile 64 rows x 256B.
    auto issue = [&](int kb) {
        uint32_t so = sbase + (uint32_t)(kb % NSTAGE) * STG_BYTES;
        #pragma unroll
        for (int i = 0; i < 4; i++) {
            int c = t + 256 * i;
            int row = c >> 3, u = c & 7;
            int gr = m0 + row;
            int sz = (gr < NN) ? 16 : 0;
            size_t gidx = (size_t)(gr < NN ? gr : 0) * DD + kb * 64 + u * 8;
            cpa16(so + swzA((uint32_t)row * 128 + u * 16), &A[gidx], sz);
        }
        #pragma unroll
        for (int i = 0; i < 4; i++) {
            int c = t + 256 * i;
            int row = c >> 4, u = c & 15;
            size_t gidx = (size_t)(kb * 64 + row) * DD + n0 + u * 8;
            cpa16(so + 16384 + swzB((uint32_t)row * 256 + u * 16), &W[gidx], 16);
        }
    };

    const int NIT = DD / 64;  // 8
    issue(0);
    asm volatile("cp.async.commit_group;");
    issue(1);
    asm volatile("cp.async.commit_group;");

    for (int kb = 0; kb < NIT; kb++) {
        if (kb + 2 < NIT) {
            issue(kb + 2);
            asm volatile("cp.async.commit_group;");
            asm volatile("cp.async.wait_group 2;");
        } else if (kb + 2 == NIT) {
            asm volatile("cp.async.wait_group 1;");
        } else {
            asm volatile("cp.async.wait_group 0;");
        }
        __syncthreads();

        uint32_t so = sbase + (uint32_t)(kb % NSTAGE) * STG_BYTES;
        uint32_t sA = so, sB = so + 16384;

        #pragma unroll
        for (int ks = 0; ks < 4; ks++) {
            int k = ks * 16;
            uint32_t ah[2][4];
            #pragma unroll
            for (int mi = 0; mi < 2; mi++) {
                uint32_t ad = (uint32_t)(wm + mi * 16 + (lane & 15)) * 128
                            + (uint32_t)(k + 8 * (lane >> 4)) * 2;
                ldsm_x4(ah[mi], sA + swzA(ad));
            }
            #pragma unroll
            for (int nj = 0; nj < 4; nj++) {
                uint32_t bh[4];
                uint32_t bd = (uint32_t)(k + (lane & 15)) * 256
                            + (uint32_t)(wn + nj * 16 + 8 * (lane >> 4)) * 2;
                ldsm_x4_t(bh, sB + swzB(bd));
                #pragma unroll
                for (int mi = 0; mi < 2; mi++)
                    #pragma unroll
                    for (int hf = 0; hf < 2; hf++)
                        mma16816(acc[mi][nj * 2 + hf], ah[mi], bh + 2 * hf);
            }
        }
        __syncthreads();
    }

    // Epilogue: add bias, store fp16
    #pragma unroll
    for (int mi = 0; mi < 2; mi++) {
        #pragma unroll
        for (int nf = 0; nf < 8; nf++) {
            int row = m0 + wm + mi * 16 + (lane >> 2);
            int col = n0 + wn + nf * 8 + (lane & 3) * 2;
            float b0 = bias[col], b1 = bias[col + 1];
            float* c = acc[mi][nf];
            if (row < NN) {
                __half2 h = __floats2half2_rn(c[0] + b0, c[1] + b1);
                *reinterpret_cast<__half2*>(&g_ht[(size_t)row * DD + col]) = h;
            }
            if (row + 8 < NN) {
                __half2 h = __floats2half2_rn(c[2] + b0, c[3] + b1);
                *reinterpret_cast<__half2*>(&g_ht[(size_t)(row + 8) * DD + col]) = h;
            }
        }
    }
}

// ---------------------------------------------------------------------------
// FUSED: CSR gather-aggregate + self-loop + LayerNorm + ReLU.
// Gathers fp16 rows (16B = 8 halves per lane-chunk), accumulates in fp32.
// ---------------------------------------------------------------------------
__device__ __forceinline__ void acc_row8(float* a, uint4 v, float w) {
    float2 f0 = __half22float2(*reinterpret_cast<__half2*>(&v.x));
    float2 f1 = __half22float2(*reinterpret_cast<__half2*>(&v.y));
    float2 f2 = __half22float2(*reinterpret_cast<__half2*>(&v.z));
    float2 f3 = __half22float2(*reinterpret_cast<__half2*>(&v.w));
    a[0] += f0.x * w; a[1] += f0.y * w;
    a[2] += f1.x * w; a[3] += f1.y * w;
    a[4] += f2.x * w; a[5] += f2.y * w;
    a[6] += f3.x * w; a[7] += f3.y * w;
}

__global__ __launch_bounds__(256) void k_agg_ln(const float* __restrict__ gamma,
                                                const float* __restrict__ beta,
                                                float* __restrict__ out, int to_out) {
    int row = blockIdx.x * 8 + (threadIdx.x >> 5);
    if (row >= NN) return;
    int lane = threadIdx.x & 31;

    float isq_r = g_isq[row];

    float acc[2][8];
    {
        const uint4* ph = reinterpret_cast<const uint4*>(&g_ht[(size_t)row * DD]);
        #pragma unroll
        for (int j = 0; j < 2; j++) {
            #pragma unroll
            for (int q = 0; q < 8; q++) acc[j][q] = 0.f;
            acc_row8(acc[j], ph[lane + 32 * j], isq_r);
        }
    }

    int e  = g_row_off[row];
    int e1 = g_row_off[row + 1];
    for (; e + 1 < e1; e += 2) {
        int s0 = g_csr_src[e];
        int s1 = g_csr_src[e + 1];
        float w0 = g_isq[s0];
        float w1 = g_isq[s1];
        const uint4* p0 = reinterpret_cast<const uint4*>(&g_ht[(size_t)s0 * DD]);
        const uint4* p1 = reinterpret_cast<const uint4*>(&g_ht[(size_t)s1 * DD]);
        #pragma unroll
        for (int j = 0; j < 2; j++) {
            uint4 v0 = p0[lane + 32 * j];
            uint4 v1 = p1[lane + 32 * j];
            acc_row8(acc[j], v0, w0);
            acc_row8(acc[j], v1, w1);
        }
    }
    if (e < e1) {
        int s0 = g_csr_src[e];
        float w0 = g_isq[s0];
        const uint4* p0 = reinterpret_cast<const uint4*>(&g_ht[(size_t)s0 * DD]);
        #pragma unroll
        for (int j = 0; j < 2; j++)
            acc_row8(acc[j], p0[lane + 32 * j], w0);
    }

    float sum = 0.f, sq = 0.f;
    #pragma unroll
    for (int j = 0; j < 2; j++)
        #pragma unroll
        for (int q = 0; q < 8; q++) {
            acc[j][q] *= isq_r;
            sum += acc[j][q];
            sq  += acc[j][q] * acc[j][q];
        }
    #pragma unroll
    for (int o = 16; o > 0; o >>= 1) {
        sum += __shfl_xor_sync(0xffffffffu, sum, o);
        sq  += __shfl_xor_sync(0xffffffffu, sq, o);
    }
    float mean = sum * (1.0f / DD);
    float var  = sq * (1.0f / DD) - mean * mean;
    float rstd = rsqrtf(var + LN_EPS);

    #pragma unroll
    for (int j = 0; j < 2; j++) {
        int col = (lane + 32 * j) * 8;
        float r[8];
        #pragma unroll
        for (int q = 0; q < 8; q++)
            r[q] = fmaxf(gamma[col + q] * (acc[j][q] - mean) * rstd + beta[col + q], 0.f);
        if (to_out) {
            float4* po = reinterpret_cast<float4*>(&out[(size_t)row * DD + col]);
            po[0] = make_float4(r[0], r[1], r[2], r[3]);
            po[1] = make_float4(r[4], r[5], r[6], r[7]);
        } else {
            size_t pidx = ((size_t)row * DD + col) >> 1;
            #pragma unroll
            for (int q = 0; q < 4; q++)
                reinterpret_cast<__half2*>(g_a)[pidx + q] =
                    __floats2half2_rn(r[2 * q], r[2 * q + 1]);
        }
    }
}

// ---------------------------------------------------------------------------
extern "C" void kernel_launch(void* const* d_in, const int* in_sizes, int n_in,
                              void* d_out, int out_size) {
    const float* x      = (const float*)d_in[0];   // [NN, DD]
    const int*   edge   = (const int*)  d_in[1];   // [2, NE]
    const float* Ws     = (const float*)d_in[2];   // [NL, DD, DD]
    const float* bs     = (const float*)d_in[3];   // [NL, DD]
    const float* gammas = (const float*)d_in[4];   // [NL, DD]
    const float* betas  = (const float*)d_in[5];   // [NL, DD]
    float* out = (float*)d_out;

    const int* src = edge;
    const int* dst = edge + NE;

    cudaFuncSetAttribute(k_gemm, cudaFuncAttributeMaxDynamicSharedMemorySize, SMEM_TOT);

    // Fork: CSR preprocessing runs on a side stream, overlapped with
    // k_conv + first GEMM. Joined before the first k_agg_ln (its only consumer).
    cudaStream_t s;
    cudaStreamCreateWithFlags(&s, cudaStreamNonBlocking);
    cudaEvent_t eFork, eJoin;
    cudaEventCreateWithFlags(&eFork, cudaEventDisableTiming);
    cudaEventCreateWithFlags(&eJoin, cudaEventDisableTiming);

    cudaEventRecord(eFork, 0);
    cudaStreamWaitEvent(s, eFork, 0);
    k_deg_init<<<(NN + 255) / 256, 256, 0, s>>>();
    k_deg_accum<<<(NE + 255) / 256, 256, 0, s>>>(dst);
    k_scan1<<<SCAN_NB, 1024, 0, s>>>();
    k_scan3<<<SCAN_NB, 1024, 0, s>>>();
    k_fill<<<(NE + 255) / 256, 256, 0, s>>>(src, dst);
    cudaEventRecord(eJoin, s);

    // Main chain
    k_conv<<<(WQUADS + XQUADS + 255) / 256, 256>>>(Ws, x);

    dim3 ggrid((NN + 127) / 128, DD / 128);
    k_gemm<<<ggrid, 256, SMEM_TOT>>>(0, bs);
    cudaStreamWaitEvent(0, eJoin, 0);   // CSR must be ready from here on
    k_agg_ln<<<(NN + 7) / 8, 256>>>(gammas, betas, out, 0);
    for (int l = 1; l < NL; l++) {
        k_gemm<<<ggrid, 256, SMEM_TOT>>>(l, bs + l * DD);
        k_agg_ln<<<(NN + 7) / 8, 256>>>(gammas + l * DD, betas + l * DD,
                                        out, l == NL - 1 ? 1 : 0);
    }

    cudaEventDestroy(eFork);
    cudaEventDestroy(eJoin);
    cudaStreamDestroy(s);
}